// round 10
// baseline (speedup 1.0000x reference)
#include <cuda_runtime.h>
#include <cuda_fp16.h>
#include <cstdint>

// ======================= config =======================
#define BM 128
#define BN 128
#define BK 64                    // fp16 elems per K-chunk: 64*2B = 128B rows
#define STAGES 3
#define NTHREADS 256

static constexpr int KDIM   = 4096;
static constexpr int NDIM   = 4096;
static constexpr int MMAX   = 8192;
static constexpr int KITERS = KDIM / BK;   // 64

#define A_BYTES     (BM * 128)             // 16384
#define B_BYTES     (BN * 128)             // 16384
#define STAGE_BYTES (A_BYTES + B_BYTES)    // 32768
#define SMEM_TOTAL  (STAGES * STAGE_BYTES) // 98304 -> 2 CTAs/SM

// scratch (allocation-free rule: __device__ globals)
__device__ __align__(1024) __half g_xh[(size_t)MMAX * KDIM];  // 64 MiB
__device__ __align__(1024) __half g_wh[(size_t)NDIM * KDIM];  // 32 MiB

// ======================= PTX helpers =======================
__device__ __forceinline__ uint32_t smem_u32(const void* p) {
    uint32_t a;
    asm("{ .reg .u64 t; cvta.to.shared.u64 t, %1; cvt.u32.u64 %0, t; }" : "=r"(a) : "l"(p));
    return a;
}

#define CP_ASYNC16(dst, src) \
    asm volatile("cp.async.cg.shared.global [%0], [%1], 16;" :: "r"(dst), "l"(src) : "memory")
#define CP_COMMIT() asm volatile("cp.async.commit_group;" ::: "memory")
#define CP_WAIT(n)  asm volatile("cp.async.wait_group %0;" :: "n"(n) : "memory")

#define LDSM4(r, addr) \
    asm volatile("ldmatrix.sync.aligned.m8n8.x4.shared.b16 {%0,%1,%2,%3}, [%4];" \
        : "=r"((r)[0]), "=r"((r)[1]), "=r"((r)[2]), "=r"((r)[3]) : "r"(addr))

// f16 x f16 -> f16 accumulate (2x issue rate vs f32-acc, measured R7)
#define MMA16816_F16(d, a, b0, b1) \
    asm volatile("mma.sync.aligned.m16n8k16.row.col.f16.f16.f16.f16 " \
        "{%0,%1},{%2,%3,%4,%5},{%6,%7},{%0,%1};" \
        : "+r"((d)[0]), "+r"((d)[1]) \
        : "r"((a)[0]), "r"((a)[1]), "r"((a)[2]), "r"((a)[3]), "r"(b0), "r"(b1))

// swizzled smem byte offset: 128B rows, 8x16B chunks, chunk XOR row&7
__device__ __forceinline__ uint32_t swz(int row, int chunk) {
    return (uint32_t)(row * 128 + ((chunk ^ (row & 7)) << 4));
}

// ======================= preprocessing (merged kernel keeps ncu on the GEMM) ===
__global__ void convert_xw_kernel(const float* __restrict__ x,
                                  const int* __restrict__ q,
                                  __half* __restrict__ xh,
                                  __half* __restrict__ wh,
                                  int n4x, int n4w) {
    const int stride = gridDim.x * blockDim.x;
    for (int i = blockIdx.x * blockDim.x + threadIdx.x; i < n4x; i += stride) {
        float4 v = reinterpret_cast<const float4*>(x)[i];
        __half2 h0 = __floats2half2_rn(v.x, v.y);
        __half2 h1 = __floats2half2_rn(v.z, v.w);
        uint2 pk;
        pk.x = *reinterpret_cast<uint32_t*>(&h0);
        pk.y = *reinterpret_cast<uint32_t*>(&h1);
        reinterpret_cast<uint2*>(xh)[i] = pk;
    }
    for (int i = blockIdx.x * blockDim.x + threadIdx.x; i < n4w; i += stride) {
        int4 v = reinterpret_cast<const int4*>(q)[i];
        // q in [0,127): exact in fp16
        __half2 h0 = __floats2half2_rn((float)v.x, (float)v.y);
        __half2 h1 = __floats2half2_rn((float)v.z, (float)v.w);
        uint2 pk;
        pk.x = *reinterpret_cast<uint32_t*>(&h0);
        pk.y = *reinterpret_cast<uint32_t*>(&h1);
        reinterpret_cast<uint2*>(wh)[i] = pk;
    }
}

// ======================= GEMM =======================
// per-thread stage load: 4 A chunks + 4 B chunks (256 thr, 128+128 rows)
// lrow in 0..31; +32 rows => +4096 smem bytes (row&7 invariant under +32)
#define LOAD_STAGE(sbase, kb) do {                                                   \
    const char* _a = (const char*)aSrc + (kb);                                       \
    const char* _b = (const char*)bSrc + (kb);                                       \
    CP_ASYNC16((sbase) + soA,                   _a);                                 \
    CP_ASYNC16((sbase) + soA + 4096,            _a + (size_t)32 * KDIM * 2);         \
    CP_ASYNC16((sbase) + soA + 8192,            _a + (size_t)64 * KDIM * 2);         \
    CP_ASYNC16((sbase) + soA + 12288,           _a + (size_t)96 * KDIM * 2);         \
    CP_ASYNC16((sbase) + A_BYTES + soA,         _b);                                 \
    CP_ASYNC16((sbase) + A_BYTES + soA + 4096,  _b + (size_t)32 * KDIM * 2);         \
    CP_ASYNC16((sbase) + A_BYTES + soA + 8192,  _b + (size_t)64 * KDIM * 2);         \
    CP_ASYNC16((sbase) + A_BYTES + soA + 12288, _b + (size_t)96 * KDIM * 2);         \
    CP_COMMIT();                                                                     \
} while (0)

__global__ void __launch_bounds__(NTHREADS, 2) qlinear_gemm(
    float* __restrict__ out,
    const float* __restrict__ scale,
    const float* __restrict__ bias,
    const __half* __restrict__ Agbase,
    const __half* __restrict__ Bgbase)
{
    extern __shared__ char smem[];
    const uint32_t sb = smem_u32(smem);
    const int tid  = threadIdx.x;
    const int warp = tid >> 5;
    const int lane = tid & 31;
    const int wm   = warp >> 2;        // 0..1  (64-row slab)
    const int wn   = warp & 3;         // 0..3  (32-col slab)
    const int bn   = blockIdx.x;
    const int bm   = blockIdx.y;

    // per-thread cp.async source bases (row/chunk fixed; only K offset advances)
    const int lrow = tid >> 3;          // 0..31
    const int lc   = tid & 7;           // 16B chunk
    const __half* aSrc = Agbase + ((size_t)(bm * BM + lrow)) * KDIM + lc * 8;
    const __half* bSrc = Bgbase + ((size_t)(bn * BN + lrow)) * KDIM + lc * 8;
    const uint32_t soA = swz(lrow, lc);

    // prologue: fill STAGES-1 = 2 stages
    LOAD_STAGE(sb,               (size_t)0);
    LOAD_STAGE(sb + STAGE_BYTES, (size_t)BK * 2);

    // f32 master accumulators: 64x32 warp tile = mt4 x nt4 x 4 (64 regs)
    float accf[4][4][4];
    uint32_t acch[4][4][2];
    #pragma unroll
    for (int mt = 0; mt < 4; mt++)
        #pragma unroll
        for (int nt = 0; nt < 4; nt++) {
            #pragma unroll
            for (int j = 0; j < 4; j++) accf[mt][nt][j] = 0.f;
            acch[mt][nt][0] = 0u;
            acch[mt][nt][1] = 0u;
        }

    const int arow0 = wm * 64 + (lane & 15);
    const int brow0 = wn * 32 + (lane & 15);
    const int chi   = lane >> 4;       // 0/1: k8-chunk within k16

    for (int kn = 0; kn < KITERS; kn++) {
        CP_WAIT(1);        // stage kn complete
        __syncthreads();

        // refill stage kn+2
        if (kn + STAGES - 1 < KITERS) {
            const int s = (kn + STAGES - 1) % STAGES;
            LOAD_STAGE(sb + (uint32_t)s * STAGE_BYTES, (size_t)(kn + STAGES - 1) * (BK * 2));
        } else {
            CP_COMMIT();   // keep group count consistent
        }

        const uint32_t abase = sb + (uint32_t)(kn % STAGES) * STAGE_BYTES;
        const uint32_t bbase = abase + A_BYTES;

        uint32_t a[4][4], b[2][4];

        // ---- ks = 0: LDSM, then drain prev chain in the LDSM shadow ----
        #pragma unroll
        for (int mt = 0; mt < 4; mt++)
            LDSM4(a[mt], abase + swz(arow0 + mt * 16, chi));
        #pragma unroll
        for (int bi = 0; bi < 2; bi++)
            LDSM4(b[bi], bbase + swz(brow0 + bi * 16, chi));

        // drain f16 chain of previous k-iter into f32 masters + rezero (regs only)
        #pragma unroll
        for (int mt = 0; mt < 4; mt++)
            #pragma unroll
            for (int nt = 0; nt < 4; nt++) {
                const float2 f0 = __half22float2(*reinterpret_cast<__half2*>(&acch[mt][nt][0]));
                const float2 f1 = __half22float2(*reinterpret_cast<__half2*>(&acch[mt][nt][1]));
                accf[mt][nt][0] += f0.x;
                accf[mt][nt][1] += f0.y;
                accf[mt][nt][2] += f1.x;
                accf[mt][nt][3] += f1.y;
                acch[mt][nt][0] = 0u;
                acch[mt][nt][1] = 0u;
            }

        #pragma unroll
        for (int mt = 0; mt < 4; mt++)
            #pragma unroll
            for (int nt = 0; nt < 4; nt++) {
                const int bi = nt >> 1, sel = nt & 1;
                MMA16816_F16(acch[mt][nt], a[mt], b[bi][sel], b[bi][sel + 2]);
            }

        // ---- ks = 1..3 ----
        #pragma unroll
        for (int ks = 1; ks < 4; ks++) {
            const int kc = ks * 2 + chi;
            #pragma unroll
            for (int mt = 0; mt < 4; mt++)
                LDSM4(a[mt], abase + swz(arow0 + mt * 16, kc));
            #pragma unroll
            for (int bi = 0; bi < 2; bi++)
                LDSM4(b[bi], bbase + swz(brow0 + bi * 16, kc));
            #pragma unroll
            for (int mt = 0; mt < 4; mt++)
                #pragma unroll
                for (int nt = 0; nt < 4; nt++) {
                    const int bi = nt >> 1, sel = nt & 1;
                    MMA16816_F16(acch[mt][nt], a[mt], b[bi][sel], b[bi][sel + 2]);
                }
        }
    }

    // final drain of the last k-iter's chain
    #pragma unroll
    for (int mt = 0; mt < 4; mt++)
        #pragma unroll
        for (int nt = 0; nt < 4; nt++) {
            const float2 f0 = __half22float2(*reinterpret_cast<__half2*>(&acch[mt][nt][0]));
            const float2 f1 = __half22float2(*reinterpret_cast<__half2*>(&acch[mt][nt][1]));
            accf[mt][nt][0] += f0.x;
            accf[mt][nt][1] += f0.y;
            accf[mt][nt][2] += f1.x;
            accf[mt][nt][3] += f1.y;
        }

    // ---------- epilogue: y = accf*scale + bias ----------
    const float sc = scale[0];
    const int qrow = lane >> 2;          // 0..7
    const int qcol = (lane & 3) * 2;     // 0,2,4,6

    #pragma unroll
    for (int mt = 0; mt < 4; mt++) {
        const int row = bm * BM + wm * 64 + mt * 16 + qrow;
        #pragma unroll
        for (int nt = 0; nt < 4; nt++) {
            const int col = bn * BN + wn * 32 + nt * 8 + qcol;
            const float b0 = bias[col], b1 = bias[col + 1];
            float2 v0, v1;
            v0.x = accf[mt][nt][0] * sc + b0;
            v0.y = accf[mt][nt][1] * sc + b1;
            v1.x = accf[mt][nt][2] * sc + b0;
            v1.y = accf[mt][nt][3] * sc + b1;
            *reinterpret_cast<float2*>(out + (size_t)row * NDIM + col) = v0;
            *reinterpret_cast<float2*>(out + (size_t)(row + 8) * NDIM + col) = v1;
        }
    }
}

// ======================= host launch =======================
extern "C" void kernel_launch(void* const* d_in, const int* in_sizes, int n_in,
                              void* d_out, int out_size) {
    const float* x  = (const float*)d_in[0];
    const int*   qw = (const int*)d_in[1];
    const float* sc = (const float*)d_in[2];
    const float* bs = (const float*)d_in[3];
    float* out = (float*)d_out;

    const int M = in_sizes[0] / KDIM;   // 8192

    void *p_xh = nullptr, *p_wh = nullptr;
    cudaGetSymbolAddress(&p_xh, g_xh);
    cudaGetSymbolAddress(&p_wh, g_wh);

    convert_xw_kernel<<<2048, 256>>>(x, qw, (__half*)p_xh, (__half*)p_wh,
                                     (M * KDIM) / 4, (NDIM * KDIM) / 4);

    static bool smem_set = false;
    if (!smem_set) {
        cudaFuncSetAttribute(qlinear_gemm, cudaFuncAttributeMaxDynamicSharedMemorySize, SMEM_TOTAL);
        smem_set = true;
    }
    dim3 grid(NDIM / BN, M / BM);   // (32, 64): bn fastest -> A-row reuse in L2
    qlinear_gemm<<<grid, NTHREADS, SMEM_TOTAL>>>(out, sc, bs,
        (const __half*)p_xh, (const __half*)p_wh);
}

// round 11
// speedup vs baseline: 1.0879x; 1.0879x over previous
#include <cuda_runtime.h>
#include <cuda_fp16.h>
#include <cstdint>

// ======================= config =======================
#define BM 128
#define BN 256
#define BK 64                    // fp16 elems per K-chunk: 64*2B = 128B rows
#define STAGES 4
#define NTHREADS 256

static constexpr int KDIM   = 4096;
static constexpr int NDIM   = 4096;
static constexpr int MMAX   = 8192;
static constexpr int KITERS = KDIM / BK;   // 64

#define A_BYTES     (BM * 128)             // 16384
#define B_BYTES     (BN * 128)             // 32768
#define STAGE_BYTES (A_BYTES + B_BYTES)    // 49152
#define SMEM_TOTAL  (STAGES * STAGE_BYTES) // 196608

// scratch (allocation-free rule: __device__ globals)
__device__ __align__(1024) __half g_xh[(size_t)MMAX * KDIM];  // 64 MiB
__device__ __align__(1024) __half g_wh[(size_t)NDIM * KDIM];  // 32 MiB

// ======================= PTX helpers =======================
__device__ __forceinline__ uint32_t smem_u32(const void* p) {
    uint32_t a;
    asm("{ .reg .u64 t; cvta.to.shared.u64 t, %1; cvt.u32.u64 %0, t; }" : "=r"(a) : "l"(p));
    return a;
}

#define CP_ASYNC16(dst, src) \
    asm volatile("cp.async.cg.shared.global [%0], [%1], 16;" :: "r"(dst), "l"(src) : "memory")
#define CP_COMMIT() asm volatile("cp.async.commit_group;" ::: "memory")
#define CP_WAIT(n)  asm volatile("cp.async.wait_group %0;" :: "n"(n) : "memory")

#define LDSM4(r, addr) \
    asm volatile("ldmatrix.sync.aligned.m8n8.x4.shared.b16 {%0,%1,%2,%3}, [%4];" \
        : "=r"((r)[0]), "=r"((r)[1]), "=r"((r)[2]), "=r"((r)[3]) : "r"(addr))

// f16 accumulate into d (d = a*b + d)
#define MMA16816_F16(d, a, b0, b1) \
    asm volatile("mma.sync.aligned.m16n8k16.row.col.f16.f16.f16.f16 " \
        "{%0,%1},{%2,%3,%4,%5},{%6,%7},{%0,%1};" \
        : "+r"((d)[0]), "+r"((d)[1]) \
        : "r"((a)[0]), "r"((a)[1]), "r"((a)[2]), "r"((a)[3]), "r"(b0), "r"(b1))

// f16 chain start: d = a*b + 0  (explicit zero C regs; no acch pre-zeroing)
#define MMA16816_F16_ZC(d, a, b0, b1) \
    asm volatile("mma.sync.aligned.m16n8k16.row.col.f16.f16.f16.f16 " \
        "{%0,%1},{%2,%3,%4,%5},{%6,%7},{%8,%9};" \
        : "=r"((d)[0]), "=r"((d)[1]) \
        : "r"((a)[0]), "r"((a)[1]), "r"((a)[2]), "r"((a)[3]), "r"(b0), "r"(b1), \
          "r"(0u), "r"(0u))

// swizzled smem byte offset: 128B rows, 8x16B chunks, chunk XOR row&7
__device__ __forceinline__ uint32_t swz(int row, int chunk) {
    return (uint32_t)(row * 128 + ((chunk ^ (row & 7)) << 4));
}

// ======================= preprocessing (merged kernel keeps ncu on the GEMM) ===
__global__ void convert_xw_kernel(const float* __restrict__ x,
                                  const int* __restrict__ q,
                                  __half* __restrict__ xh,
                                  __half* __restrict__ wh,
                                  int n4x, int n4w) {
    const int stride = gridDim.x * blockDim.x;
    for (int i = blockIdx.x * blockDim.x + threadIdx.x; i < n4x; i += stride) {
        float4 v = reinterpret_cast<const float4*>(x)[i];
        __half2 h0 = __floats2half2_rn(v.x, v.y);
        __half2 h1 = __floats2half2_rn(v.z, v.w);
        uint2 pk;
        pk.x = *reinterpret_cast<uint32_t*>(&h0);
        pk.y = *reinterpret_cast<uint32_t*>(&h1);
        reinterpret_cast<uint2*>(xh)[i] = pk;
    }
    for (int i = blockIdx.x * blockDim.x + threadIdx.x; i < n4w; i += stride) {
        int4 v = reinterpret_cast<const int4*>(q)[i];
        // q in [0,127): exact in fp16
        __half2 h0 = __floats2half2_rn((float)v.x, (float)v.y);
        __half2 h1 = __floats2half2_rn((float)v.z, (float)v.w);
        uint2 pk;
        pk.x = *reinterpret_cast<uint32_t*>(&h0);
        pk.y = *reinterpret_cast<uint32_t*>(&h1);
        reinterpret_cast<uint2*>(wh)[i] = pk;
    }
}

// ======================= GEMM =======================
// per-thread stage load (256 thr): lrow 0..31, 4 A chunks + 8 B chunks
// +32 rows => +4096 smem bytes (row&7 invariant under +32)
#define LOAD_STAGE(sbase, kb) do {                                                   \
    const char* _a = (const char*)aSrc + (kb);                                       \
    const char* _b = (const char*)bSrc + (kb);                                       \
    CP_ASYNC16((sbase) + soA,                    _a);                                \
    CP_ASYNC16((sbase) + soA + 4096,             _a + (size_t)32  * KDIM * 2);       \
    CP_ASYNC16((sbase) + soA + 8192,             _a + (size_t)64  * KDIM * 2);       \
    CP_ASYNC16((sbase) + soA + 12288,            _a + (size_t)96  * KDIM * 2);       \
    CP_ASYNC16((sbase) + A_BYTES + soA,          _b);                                \
    CP_ASYNC16((sbase) + A_BYTES + soA + 4096,   _b + (size_t)32  * KDIM * 2);       \
    CP_ASYNC16((sbase) + A_BYTES + soA + 8192,   _b + (size_t)64  * KDIM * 2);       \
    CP_ASYNC16((sbase) + A_BYTES + soA + 12288,  _b + (size_t)96  * KDIM * 2);       \
    CP_ASYNC16((sbase) + A_BYTES + soA + 16384,  _b + (size_t)128 * KDIM * 2);       \
    CP_ASYNC16((sbase) + A_BYTES + soA + 20480,  _b + (size_t)160 * KDIM * 2);       \
    CP_ASYNC16((sbase) + A_BYTES + soA + 24576,  _b + (size_t)192 * KDIM * 2);       \
    CP_ASYNC16((sbase) + A_BYTES + soA + 28672,  _b + (size_t)224 * KDIM * 2);       \
    CP_COMMIT();                                                                     \
} while (0)

__global__ void __launch_bounds__(NTHREADS, 1) qlinear_gemm(
    float* __restrict__ out,
    const float* __restrict__ scale,
    const float* __restrict__ bias,
    const __half* __restrict__ Agbase,
    const __half* __restrict__ Bgbase)
{
    extern __shared__ char smem[];
    const uint32_t sb = smem_u32(smem);
    const int tid  = threadIdx.x;
    const int warp = tid >> 5;
    const int lane = tid & 31;
    const int wm   = warp >> 2;        // 0..1  (64-row slab)
    const int wn   = warp & 3;         // 0..3  (64-col slab)
    const int bn   = blockIdx.x;
    const int bm   = blockIdx.y;

    // per-thread cp.async source bases (row/chunk fixed; only K offset advances)
    const int lrow = tid >> 3;          // 0..31
    const int lc   = tid & 7;           // 16B chunk
    const __half* aSrc = Agbase + ((size_t)(bm * BM + lrow)) * KDIM + lc * 8;
    const __half* bSrc = Bgbase + ((size_t)(bn * BN + lrow)) * KDIM + lc * 8;
    const uint32_t soA = swz(lrow, lc);

    // prologue: fill STAGES-1 = 3 stages
    #pragma unroll
    for (int s = 0; s < STAGES - 1; s++)
        LOAD_STAGE(sb + s * STAGE_BYTES, (size_t)s * (BK * 2));

    // f32 masters (128 regs) + f16 chain regs (64)
    float accf[4][8][4];
    uint32_t acch[4][8][2];
    #pragma unroll
    for (int mt = 0; mt < 4; mt++)
        #pragma unroll
        for (int nt = 0; nt < 8; nt++) {
            #pragma unroll
            for (int j = 0; j < 4; j++) accf[mt][nt][j] = 0.f;
            acch[mt][nt][0] = 0u;   // kn=0 shadow-drain reads zeros
            acch[mt][nt][1] = 0u;
        }

    const int arow0 = wm * 64 + (lane & 15);
    const int brow0 = wn * 64 + (lane & 15);
    const int chi   = lane >> 4;        // 0/1: k8-chunk within k16
    const int kswz  = (warp & 1) << 1;  // warp-phase stagger: odd warps do ks 2,3,0,1

    for (int kn = 0; kn < KITERS; kn++) {
        CP_WAIT(STAGES - 2);
        __syncthreads();

        if (kn + STAGES - 1 < KITERS)
            LOAD_STAGE(sb + (uint32_t)((kn + STAGES - 1) & (STAGES - 1)) * STAGE_BYTES,
                       (size_t)(kn + STAGES - 1) * (BK * 2));
        else
            CP_COMMIT();   // keep group count consistent

        const uint32_t abase = sb + (uint32_t)(kn & (STAGES - 1)) * STAGE_BYTES;
        const uint32_t bbase = abase + A_BYTES;

        uint32_t a[4][4], b[4][4];

        // ---- ksi = 0: LDSM, drain prev chain in LDSM shadow, chain-start MMAs ----
        {
            const int kc = kswz * 2 + chi;   // ks = kswz
            #pragma unroll
            for (int mt = 0; mt < 4; mt++)
                LDSM4(a[mt], abase + swz(arow0 + mt * 16, kc));
            #pragma unroll
            for (int bi = 0; bi < 4; bi++)
                LDSM4(b[bi], bbase + swz(brow0 + bi * 16, kc));

            // drain previous k-iter's f16 chain into f32 masters (regs only)
            #pragma unroll
            for (int mt = 0; mt < 4; mt++)
                #pragma unroll
                for (int nt = 0; nt < 8; nt++) {
                    const float2 f0 = __half22float2(*reinterpret_cast<__half2*>(&acch[mt][nt][0]));
                    const float2 f1 = __half22float2(*reinterpret_cast<__half2*>(&acch[mt][nt][1]));
                    accf[mt][nt][0] += f0.x;
                    accf[mt][nt][1] += f0.y;
                    accf[mt][nt][2] += f1.x;
                    accf[mt][nt][3] += f1.y;
                }

            #pragma unroll
            for (int mt = 0; mt < 4; mt++)
                #pragma unroll
                for (int nt = 0; nt < 8; nt++) {
                    const int bi = nt >> 1, sel = nt & 1;
                    MMA16816_F16_ZC(acch[mt][nt], a[mt], b[bi][sel], b[bi][sel + 2]);
                }
        }

        // ---- ksi = 1..3 (staggered order) ----
        #pragma unroll
        for (int ksi = 1; ksi < 4; ksi++) {
            const int kc = ((ksi + kswz) & 3) * 2 + chi;
            #pragma unroll
            for (int mt = 0; mt < 4; mt++)
                LDSM4(a[mt], abase + swz(arow0 + mt * 16, kc));
            #pragma unroll
            for (int bi = 0; bi < 4; bi++)
                LDSM4(b[bi], bbase + swz(brow0 + bi * 16, kc));
            #pragma unroll
            for (int mt = 0; mt < 4; mt++)
                #pragma unroll
                for (int nt = 0; nt < 8; nt++) {
                    const int bi = nt >> 1, sel = nt & 1;
                    MMA16816_F16(acch[mt][nt], a[mt], b[bi][sel], b[bi][sel + 2]);
                }
        }
    }

    // final drain of the last k-iter's chain
    #pragma unroll
    for (int mt = 0; mt < 4; mt++)
        #pragma unroll
        for (int nt = 0; nt < 8; nt++) {
            const float2 f0 = __half22float2(*reinterpret_cast<__half2*>(&acch[mt][nt][0]));
            const float2 f1 = __half22float2(*reinterpret_cast<__half2*>(&acch[mt][nt][1]));
            accf[mt][nt][0] += f0.x;
            accf[mt][nt][1] += f0.y;
            accf[mt][nt][2] += f1.x;
            accf[mt][nt][3] += f1.y;
        }

    // ---------- epilogue: y = accf*scale + bias ----------
    const float sc = scale[0];
    const int qrow = lane >> 2;          // 0..7
    const int qcol = (lane & 3) * 2;     // 0,2,4,6

    #pragma unroll
    for (int mt = 0; mt < 4; mt++) {
        const int row = bm * BM + wm * 64 + mt * 16 + qrow;
        #pragma unroll
        for (int nt = 0; nt < 8; nt++) {
            const int col = bn * BN + wn * 64 + nt * 8 + qcol;
            const float b0 = bias[col], b1 = bias[col + 1];
            float2 v0, v1;
            v0.x = accf[mt][nt][0] * sc + b0;
            v0.y = accf[mt][nt][1] * sc + b1;
            v1.x = accf[mt][nt][2] * sc + b0;
            v1.y = accf[mt][nt][3] * sc + b1;
            *reinterpret_cast<float2*>(out + (size_t)row * NDIM + col) = v0;
            *reinterpret_cast<float2*>(out + (size_t)(row + 8) * NDIM + col) = v1;
        }
    }
}

// ======================= host launch =======================
extern "C" void kernel_launch(void* const* d_in, const int* in_sizes, int n_in,
                              void* d_out, int out_size) {
    const float* x  = (const float*)d_in[0];
    const int*   qw = (const int*)d_in[1];
    const float* sc = (const float*)d_in[2];
    const float* bs = (const float*)d_in[3];
    float* out = (float*)d_out;

    const int M = in_sizes[0] / KDIM;   // 8192

    void *p_xh = nullptr, *p_wh = nullptr;
    cudaGetSymbolAddress(&p_xh, g_xh);
    cudaGetSymbolAddress(&p_wh, g_wh);

    convert_xw_kernel<<<2048, 256>>>(x, qw, (__half*)p_xh, (__half*)p_wh,
                                     (M * KDIM) / 4, (NDIM * KDIM) / 4);

    static bool smem_set = false;
    if (!smem_set) {
        cudaFuncSetAttribute(qlinear_gemm, cudaFuncAttributeMaxDynamicSharedMemorySize, SMEM_TOTAL);
        smem_set = true;
    }
    dim3 grid(NDIM / BN, M / BM);   // (16, 64): bn fastest -> A-row reuse in L2
    qlinear_gemm<<<grid, NTHREADS, SMEM_TOTAL>>>(out, sc, bs,
        (const __half*)p_xh, (const __half*)p_wh);
}

// round 12
// speedup vs baseline: 1.2512x; 1.1501x over previous
#include <cuda_runtime.h>
#include <cuda_fp16.h>
#include <cstdint>
#include <cstring>

// ======================= config =======================
#define BM 128
#define BN 256
#define BK 64                    // fp16 elems per K-chunk: 64*2B = 128B rows
#define STAGES 4
#define NTHREADS 256

static constexpr int KDIM   = 4096;
static constexpr int NDIM   = 4096;
static constexpr int MMAX   = 8192;
static constexpr int KITERS = KDIM / BK;   // 64

#define A_BYTES     (BM * 128)             // 16384
#define B_BYTES     (BN * 128)             // 32768
#define STAGE_BYTES (A_BYTES + B_BYTES)    // 49152
#define SMEM_TOTAL  (STAGES * STAGE_BYTES) // 196608

// scratch (allocation-free rule: __device__ globals)
__device__ __align__(1024) __half g_xh[(size_t)MMAX * KDIM];  // 64 MiB
__device__ __align__(1024) __half g_wh[(size_t)NDIM * KDIM];  // 32 MiB

// ======================= PTX helpers =======================
__device__ __forceinline__ uint32_t smem_u32(const void* p) {
    uint32_t a;
    asm("{ .reg .u64 t; cvta.to.shared.u64 t, %1; cvt.u32.u64 %0, t; }" : "=r"(a) : "l"(p));
    return a;
}

#define CP_ASYNC16(dst, src) \
    asm volatile("cp.async.cg.shared.global [%0], [%1], 16;" :: "r"(dst), "l"(src) : "memory")
#define CP_COMMIT() asm volatile("cp.async.commit_group;" ::: "memory")
#define CP_WAIT(n)  asm volatile("cp.async.wait_group %0;" :: "n"(n) : "memory")

#define LDSM4(r, addr) \
    asm volatile("ldmatrix.sync.aligned.m8n8.x4.shared.b16 {%0,%1,%2,%3}, [%4];" \
        : "=r"((r)[0]), "=r"((r)[1]), "=r"((r)[2]), "=r"((r)[3]) : "r"(addr))

// f16 accumulate into d (d = a*b + d)
#define MMA16816_F16(d, a, b0, b1) \
    asm volatile("mma.sync.aligned.m16n8k16.row.col.f16.f16.f16.f16 " \
        "{%0,%1},{%2,%3,%4,%5},{%6,%7},{%0,%1};" \
        : "+r"((d)[0]), "+r"((d)[1]) \
        : "r"((a)[0]), "r"((a)[1]), "r"((a)[2]), "r"((a)[3]), "r"(b0), "r"(b1))

// f16 chain start: d = a*b + 0 (explicit zero C; no pre-zeroing of acch)
#define MMA16816_F16_ZC(d, a, b0, b1) \
    asm volatile("mma.sync.aligned.m16n8k16.row.col.f16.f16.f16.f16 " \
        "{%0,%1},{%2,%3,%4,%5},{%6,%7},{%8,%9};" \
        : "=r"((d)[0]), "=r"((d)[1]) \
        : "r"((a)[0]), "r"((a)[1]), "r"((a)[2]), "r"((a)[3]), "r"(b0), "r"(b1), \
          "r"(0u), "r"(0u))

// packed f32x2 add (sm_103a native): acc64 += f64 (two fp32 lanes)
#define ADD_F32X2(acc64, f64) \
    asm("add.rn.f32x2 %0, %0, %1;" : "+l"(acc64) : "l"(f64))

// swizzled smem byte offset: 128B rows, 8x16B chunks, chunk XOR row&7
__device__ __forceinline__ uint32_t swz(int row, int chunk) {
    return (uint32_t)(row * 128 + ((chunk ^ (row & 7)) << 4));
}

__device__ __forceinline__ unsigned long long pack_f2(float2 v) {
    unsigned long long r;
    asm("mov.b64 %0, {%1, %2};" : "=l"(r) : "f"(v.x), "f"(v.y));
    return r;
}
__device__ __forceinline__ float2 unpack_f2(unsigned long long v) {
    float2 r;
    asm("mov.b64 {%0, %1}, %2;" : "=f"(r.x), "=f"(r.y) : "l"(v));
    return r;
}

// ======================= preprocessing (merged kernel keeps ncu on the GEMM) ===
__global__ void convert_xw_kernel(const float* __restrict__ x,
                                  const int* __restrict__ q,
                                  __half* __restrict__ xh,
                                  __half* __restrict__ wh,
                                  int n4x, int n4w) {
    const int stride = gridDim.x * blockDim.x;
    for (int i = blockIdx.x * blockDim.x + threadIdx.x; i < n4x; i += stride) {
        float4 v = reinterpret_cast<const float4*>(x)[i];
        __half2 h0 = __floats2half2_rn(v.x, v.y);
        __half2 h1 = __floats2half2_rn(v.z, v.w);
        uint2 pk;
        pk.x = *reinterpret_cast<uint32_t*>(&h0);
        pk.y = *reinterpret_cast<uint32_t*>(&h1);
        reinterpret_cast<uint2*>(xh)[i] = pk;
    }
    for (int i = blockIdx.x * blockDim.x + threadIdx.x; i < n4w; i += stride) {
        int4 v = reinterpret_cast<const int4*>(q)[i];
        // q in [0,127): exact in fp16
        __half2 h0 = __floats2half2_rn((float)v.x, (float)v.y);
        __half2 h1 = __floats2half2_rn((float)v.z, (float)v.w);
        uint2 pk;
        pk.x = *reinterpret_cast<uint32_t*>(&h0);
        pk.y = *reinterpret_cast<uint32_t*>(&h1);
        reinterpret_cast<uint2*>(wh)[i] = pk;
    }
}

// ======================= GEMM =======================
// per-thread stage load (256 thr): lrow 0..31, 4 A chunks + 8 B chunks
// +32 rows => +4096 smem bytes (row&7 invariant under +32)
#define LOAD_STAGE(sbase, kb) do {                                                   \
    const char* _a = (const char*)aSrc + (kb);                                       \
    const char* _b = (const char*)bSrc + (kb);                                       \
    CP_ASYNC16((sbase) + soA,                    _a);                                \
    CP_ASYNC16((sbase) + soA + 4096,             _a + (size_t)32  * KDIM * 2);       \
    CP_ASYNC16((sbase) + soA + 8192,             _a + (size_t)64  * KDIM * 2);       \
    CP_ASYNC16((sbase) + soA + 12288,            _a + (size_t)96  * KDIM * 2);       \
    CP_ASYNC16((sbase) + A_BYTES + soA,          _b);                                \
    CP_ASYNC16((sbase) + A_BYTES + soA + 4096,   _b + (size_t)32  * KDIM * 2);       \
    CP_ASYNC16((sbase) + A_BYTES + soA + 8192,   _b + (size_t)64  * KDIM * 2);       \
    CP_ASYNC16((sbase) + A_BYTES + soA + 12288,  _b + (size_t)96  * KDIM * 2);       \
    CP_ASYNC16((sbase) + A_BYTES + soA + 16384,  _b + (size_t)128 * KDIM * 2);       \
    CP_ASYNC16((sbase) + A_BYTES + soA + 20480,  _b + (size_t)160 * KDIM * 2);       \
    CP_ASYNC16((sbase) + A_BYTES + soA + 24576,  _b + (size_t)192 * KDIM * 2);       \
    CP_ASYNC16((sbase) + A_BYTES + soA + 28672,  _b + (size_t)224 * KDIM * 2);       \
    CP_COMMIT();                                                                     \
} while (0)

__global__ void __launch_bounds__(NTHREADS, 1) qlinear_gemm(
    float* __restrict__ out,
    const float* __restrict__ scale,
    const float* __restrict__ bias,
    const __half* __restrict__ Agbase,
    const __half* __restrict__ Bgbase)
{
    extern __shared__ char smem[];
    const uint32_t sb = smem_u32(smem);
    const int tid  = threadIdx.x;
    const int warp = tid >> 5;
    const int lane = tid & 31;
    const int wm   = warp >> 2;        // 0..1  (64-row slab)
    const int wn   = warp & 3;         // 0..3  (64-col slab)
    const int bn   = blockIdx.x;
    const int bm   = blockIdx.y;

    // per-thread cp.async source bases (row/chunk fixed; only K offset advances)
    const int lrow = tid >> 3;          // 0..31
    const int lc   = tid & 7;           // 16B chunk
    const __half* aSrc = Agbase + ((size_t)(bm * BM + lrow)) * KDIM + lc * 8;
    const __half* bSrc = Bgbase + ((size_t)(bn * BN + lrow)) * KDIM + lc * 8;
    const uint32_t soA = swz(lrow, lc);

    // prologue: fill STAGES-1 = 3 stages
    #pragma unroll
    for (int s = 0; s < STAGES - 1; s++)
        LOAD_STAGE(sb + s * STAGE_BYTES, (size_t)s * (BK * 2));

    // f32 masters as packed f32x2 pairs (64 x 64-bit = 128 regs)
    // accf2[mt][nt][0] = cols (qcol,qcol+1) @ row qrow ; [1] = @ row qrow+8
    unsigned long long accf2[4][8][2];
    uint32_t acch[4][8][2];
    #pragma unroll
    for (int mt = 0; mt < 4; mt++)
        #pragma unroll
        for (int nt = 0; nt < 8; nt++) {
            accf2[mt][nt][0] = 0ull;   // (0.0f, 0.0f)
            accf2[mt][nt][1] = 0ull;
            acch[mt][nt][0] = 0u;      // kn=0 drain reads zeros
            acch[mt][nt][1] = 0u;
        }

    const int arow0 = wm * 64 + (lane & 15);
    const int brow0 = wn * 64 + (lane & 15);
    const int chi   = lane >> 4;       // 0/1: k8-chunk within k16

    for (int kn = 0; kn < KITERS; kn++) {
        CP_WAIT(STAGES - 2);
        __syncthreads();

        if (kn + STAGES - 1 < KITERS)
            LOAD_STAGE(sb + (uint32_t)((kn + STAGES - 1) & (STAGES - 1)) * STAGE_BYTES,
                       (size_t)(kn + STAGES - 1) * (BK * 2));
        else
            CP_COMMIT();   // keep group count consistent

        const uint32_t abase = sb + (uint32_t)(kn & (STAGES - 1)) * STAGE_BYTES;
        const uint32_t bbase = abase + A_BYTES;
        const bool chain_start = (kn & 1) == 0;   // chains span 2 k-iters (K=128)

        #pragma unroll
        for (int ks = 0; ks < 4; ks++) {           // 4 x k16 = BK 64
            const int kc = ks * 2 + chi;
            uint32_t a[4][4], b[4][4];
            #pragma unroll
            for (int mt = 0; mt < 4; mt++)
                LDSM4(a[mt], abase + swz(arow0 + mt * 16, kc));
            #pragma unroll
            for (int bi = 0; bi < 4; bi++)
                LDSM4(b[bi], bbase + swz(brow0 + bi * 16, kc));

            if (chain_start && ks == 0) {
                // drain previous 2-iter chain into packed f32 masters, then ZC restart
                #pragma unroll
                for (int mt = 0; mt < 4; mt++)
                    #pragma unroll
                    for (int nt = 0; nt < 8; nt++) {
                        const float2 f0 = __half22float2(*reinterpret_cast<__half2*>(&acch[mt][nt][0]));
                        const float2 f1 = __half22float2(*reinterpret_cast<__half2*>(&acch[mt][nt][1]));
                        ADD_F32X2(accf2[mt][nt][0], pack_f2(f0));
                        ADD_F32X2(accf2[mt][nt][1], pack_f2(f1));
                    }
                #pragma unroll
                for (int mt = 0; mt < 4; mt++)
                    #pragma unroll
                    for (int nt = 0; nt < 8; nt++) {
                        const int bi = nt >> 1, sel = nt & 1;
                        MMA16816_F16_ZC(acch[mt][nt], a[mt], b[bi][sel], b[bi][sel + 2]);
                    }
            } else {
                #pragma unroll
                for (int mt = 0; mt < 4; mt++)
                    #pragma unroll
                    for (int nt = 0; nt < 8; nt++) {
                        const int bi = nt >> 1, sel = nt & 1;
                        MMA16816_F16(acch[mt][nt], a[mt], b[bi][sel], b[bi][sel + 2]);
                    }
            }
        }
    }

    // final drain of the last chain
    #pragma unroll
    for (int mt = 0; mt < 4; mt++)
        #pragma unroll
        for (int nt = 0; nt < 8; nt++) {
            const float2 f0 = __half22float2(*reinterpret_cast<__half2*>(&acch[mt][nt][0]));
            const float2 f1 = __half22float2(*reinterpret_cast<__half2*>(&acch[mt][nt][1]));
            ADD_F32X2(accf2[mt][nt][0], pack_f2(f0));
            ADD_F32X2(accf2[mt][nt][1], pack_f2(f1));
        }

    // ---------- epilogue: y = accf*scale + bias ----------
    const float sc = scale[0];
    const int qrow = lane >> 2;          // 0..7
    const int qcol = (lane & 3) * 2;     // 0,2,4,6

    #pragma unroll
    for (int mt = 0; mt < 4; mt++) {
        const int row = bm * BM + wm * 64 + mt * 16 + qrow;
        #pragma unroll
        for (int nt = 0; nt < 8; nt++) {
            const int col = bn * BN + wn * 64 + nt * 8 + qcol;
            const float b0 = bias[col], b1 = bias[col + 1];
            const float2 p0 = unpack_f2(accf2[mt][nt][0]);
            const float2 p1 = unpack_f2(accf2[mt][nt][1]);
            float2 v0, v1;
            v0.x = p0.x * sc + b0;
            v0.y = p0.y * sc + b1;
            v1.x = p1.x * sc + b0;
            v1.y = p1.y * sc + b1;
            *reinterpret_cast<float2*>(out + (size_t)row * NDIM + col) = v0;
            *reinterpret_cast<float2*>(out + (size_t)(row + 8) * NDIM + col) = v1;
        }
    }
}

// ======================= host launch =======================
extern "C" void kernel_launch(void* const* d_in, const int* in_sizes, int n_in,
                              void* d_out, int out_size) {
    const float* x  = (const float*)d_in[0];
    const int*   qw = (const int*)d_in[1];
    const float* sc = (const float*)d_in[2];
    const float* bs = (const float*)d_in[3];
    float* out = (float*)d_out;

    const int M = in_sizes[0] / KDIM;   // 8192

    void *p_xh = nullptr, *p_wh = nullptr;
    cudaGetSymbolAddress(&p_xh, g_xh);
    cudaGetSymbolAddress(&p_wh, g_wh);

    convert_xw_kernel<<<2048, 256>>>(x, qw, (__half*)p_xh, (__half*)p_wh,
                                     (M * KDIM) / 4, (NDIM * KDIM) / 4);

    static bool smem_set = false;
    if (!smem_set) {
        cudaFuncSetAttribute(qlinear_gemm, cudaFuncAttributeMaxDynamicSharedMemorySize, SMEM_TOTAL);
        smem_set = true;
    }
    dim3 grid(NDIM / BN, M / BM);   // (16, 64): bn fastest -> A-row reuse in L2
    qlinear_gemm<<<grid, NTHREADS, SMEM_TOTAL>>>(out, sc, bs,
        (const __half*)p_xh, (const __half*)p_wh);
}

// round 13
// speedup vs baseline: 1.2981x; 1.0375x over previous
#include <cuda_runtime.h>
#include <cuda_fp16.h>
#include <cstdint>

// ======================= config =======================
#define BM 128
#define BN 256
#define BK 64                    // fp16 elems per K-chunk: 64*2B = 128B rows
#define STAGES 4

static constexpr int KDIM   = 4096;
static constexpr int NDIM   = 4096;
static constexpr int MMAX   = 8192;
static constexpr int KITERS = KDIM / BK;   // 64

#define A_BYTES     (BM * 128)             // 16384
#define B_BYTES     (BN * 128)             // 32768
#define STAGE_BYTES (A_BYTES + B_BYTES)    // 49152
#define SMEM_TOTAL  (STAGES * STAGE_BYTES) // 196608

// scratch (allocation-free rule: __device__ globals)
__device__ __align__(1024) __half g_xh[(size_t)MMAX * KDIM];  // 64 MiB
__device__ __align__(1024) __half g_wh[(size_t)NDIM * KDIM];  // 32 MiB

// ======================= PTX helpers =======================
__device__ __forceinline__ uint32_t smem_u32(const void* p) {
    uint32_t a;
    asm("{ .reg .u64 t; cvta.to.shared.u64 t, %1; cvt.u32.u64 %0, t; }" : "=r"(a) : "l"(p));
    return a;
}

#define CP_ASYNC16(dst, src) \
    asm volatile("cp.async.cg.shared.global [%0], [%1], 16;" :: "r"(dst), "l"(src) : "memory")
#define CP_COMMIT() asm volatile("cp.async.commit_group;" ::: "memory")
#define CP_WAIT(n)  asm volatile("cp.async.wait_group %0;" :: "n"(n) : "memory")

#define LDSM4(r, addr) \
    asm volatile("ldmatrix.sync.aligned.m8n8.x4.shared.b16 {%0,%1,%2,%3}, [%4];" \
        : "=r"((r)[0]), "=r"((r)[1]), "=r"((r)[2]), "=r"((r)[3]) : "r"(addr))

// f16 x f16 -> f16 accumulate (2x issue rate vs f32-acc, measured R7)
#define MMA16816_F16(d, a, b0, b1) \
    asm volatile("mma.sync.aligned.m16n8k16.row.col.f16.f16.f16.f16 " \
        "{%0,%1},{%2,%3,%4,%5},{%6,%7},{%0,%1};" \
        : "+r"((d)[0]), "+r"((d)[1]) \
        : "r"((a)[0]), "r"((a)[1]), "r"((a)[2]), "r"((a)[3]), "r"(b0), "r"(b1))

// swizzled smem byte offset: 128B rows, 8x16B chunks, chunk XOR row&7
__device__ __forceinline__ uint32_t swz(int row, int chunk) {
    return (uint32_t)(row * 128 + ((chunk ^ (row & 7)) << 4));
}

// ======================= preprocessing (merged kernel keeps ncu on the GEMM) ===
__global__ void convert_xw_kernel(const float* __restrict__ x,
                                  const int* __restrict__ q,
                                  __half* __restrict__ xh,
                                  __half* __restrict__ wh,
                                  int n4x, int n4w) {
    const int stride = gridDim.x * blockDim.x;
    for (int i = blockIdx.x * blockDim.x + threadIdx.x; i < n4x; i += stride) {
        float4 v = reinterpret_cast<const float4*>(x)[i];
        __half2 h0 = __floats2half2_rn(v.x, v.y);
        __half2 h1 = __floats2half2_rn(v.z, v.w);
        uint2 pk;
        pk.x = *reinterpret_cast<uint32_t*>(&h0);
        pk.y = *reinterpret_cast<uint32_t*>(&h1);
        reinterpret_cast<uint2*>(xh)[i] = pk;
    }
    for (int i = blockIdx.x * blockDim.x + threadIdx.x; i < n4w; i += stride) {
        int4 v = reinterpret_cast<const int4*>(q)[i];
        // q in [0,127): exact in fp16
        __half2 h0 = __floats2half2_rn((float)v.x, (float)v.y);
        __half2 h1 = __floats2half2_rn((float)v.z, (float)v.w);
        uint2 pk;
        pk.x = *reinterpret_cast<uint32_t*>(&h0);
        pk.y = *reinterpret_cast<uint32_t*>(&h1);
        reinterpret_cast<uint2*>(wh)[i] = pk;
    }
}

// ======================= GEMM =======================
__device__ __forceinline__ void load_stage(uint32_t sb, int s, int kn, int tid,
                                           const __half* Ag, const __half* Bg) {
    const uint32_t base = sb + (uint32_t)s * STAGE_BYTES;
    const int row = tid >> 3;          // 0..31
    const int c   = tid & 7;           // 16B chunk
    const int kcol = kn * BK + c * 8;  // fp16 column
    #pragma unroll
    for (int it = 0; it < BM / 32; it++) {          // A: 128 rows
        const int r = row + it * 32;
        CP_ASYNC16(base + swz(r, c), Ag + (size_t)r * KDIM + kcol);
    }
    #pragma unroll
    for (int it = 0; it < BN / 32; it++) {          // B: 256 rows
        const int r = row + it * 32;
        CP_ASYNC16(base + A_BYTES + swz(r, c), Bg + (size_t)r * KDIM + kcol);
    }
    CP_COMMIT();
}

__global__ void __launch_bounds__(256, 1) qlinear_gemm(
    float* __restrict__ out,
    const float* __restrict__ scale,
    const float* __restrict__ bias,
    const __half* __restrict__ Agbase,
    const __half* __restrict__ Bgbase)
{
    extern __shared__ char smem[];
    const uint32_t sb = smem_u32(smem);
    const int tid  = threadIdx.x;
    const int warp = tid >> 5;
    const int lane = tid & 31;
    const int wm   = warp >> 2;        // 0..1  (64-row slab)
    const int wn   = warp & 3;         // 0..3  (64-col slab)
    const int bn   = blockIdx.x;
    const int bm   = blockIdx.y;

    const __half* Ag = Agbase + (size_t)bm * BM * KDIM;
    const __half* Bg = Bgbase + (size_t)bn * BN * KDIM;

    // prologue: fill STAGES-1 stages
    #pragma unroll
    for (int s = 0; s < STAGES - 1; s++) load_stage(sb, s, s, tid, Ag, Bg);

    // f32 master accumulators: 64x64 warp tile = mt4 x nt8 x 4
    float accf[4][8][4];
    #pragma unroll
    for (int mt = 0; mt < 4; mt++)
        #pragma unroll
        for (int nt = 0; nt < 8; nt++)
            #pragma unroll
            for (int j = 0; j < 4; j++) accf[mt][nt][j] = 0.f;

    const int arow0 = wm * 64 + (lane & 15);
    const int brow0 = wn * 64 + (lane & 15);
    const int chi   = lane >> 4;       // 0/1: k8-chunk within k16

    // warp-phase stagger: the two warps sharing an SMSP are w and w+4 (same
    // warp&3, different wm). Give them opposite ks phase so one warp's MMA
    // burst covers the other's LDSM burst on the shared crossbar/scheduler.
    const int kswz = ((warp >> 2) & 1) << 1;   // 0 or 2

    for (int kn = 0; kn < KITERS; kn++) {
        CP_WAIT(STAGES - 2);
        __syncthreads();   // single sync per iter: stage (kn-1)%4 already consumed

        if (kn + STAGES - 1 < KITERS)
            load_stage(sb, (kn + STAGES - 1) % STAGES, kn + STAGES - 1, tid, Ag, Bg);
        else
            CP_COMMIT();   // keep group count consistent

        const uint32_t abase = sb + (uint32_t)(kn % STAGES) * STAGE_BYTES;
        const uint32_t bbase = abase + A_BYTES;

        // f16 accumulators for this k-iter (drained to f32 below)
        uint32_t acch[4][8][2];
        #pragma unroll
        for (int mt = 0; mt < 4; mt++)
            #pragma unroll
            for (int nt = 0; nt < 8; nt++) {
                acch[mt][nt][0] = 0u;
                acch[mt][nt][1] = 0u;
            }

        #pragma unroll
        for (int ksi = 0; ksi < 4; ksi++) {        // 4 x k16 = BK 64 (staggered order)
            const int kc = ((ksi + kswz) & 3) * 2 + chi;
            uint32_t a[4][4], b[4][4];
            #pragma unroll
            for (int mt = 0; mt < 4; mt++)
                LDSM4(a[mt], abase + swz(arow0 + mt * 16, kc));
            #pragma unroll
            for (int bi = 0; bi < 4; bi++)
                LDSM4(b[bi], bbase + swz(brow0 + bi * 16, kc));
            #pragma unroll
            for (int mt = 0; mt < 4; mt++) {
                #pragma unroll
                for (int nt = 0; nt < 8; nt++) {
                    const int bi = nt >> 1, sel = nt & 1;
                    MMA16816_F16(acch[mt][nt], a[mt], b[bi][sel], b[bi][sel + 2]);
                }
            }
        }

        // drain f16 -> f32 masters
        #pragma unroll
        for (int mt = 0; mt < 4; mt++)
            #pragma unroll
            for (int nt = 0; nt < 8; nt++) {
                const float2 f0 = __half22float2(*reinterpret_cast<__half2*>(&acch[mt][nt][0]));
                const float2 f1 = __half22float2(*reinterpret_cast<__half2*>(&acch[mt][nt][1]));
                accf[mt][nt][0] += f0.x;
                accf[mt][nt][1] += f0.y;
                accf[mt][nt][2] += f1.x;
                accf[mt][nt][3] += f1.y;
            }
    }

    // ---------- epilogue: y = accf*scale + bias ----------
    const float sc = scale[0];
    const int qrow = lane >> 2;          // 0..7
    const int qcol = (lane & 3) * 2;     // 0,2,4,6

    #pragma unroll
    for (int mt = 0; mt < 4; mt++) {
        const int row = bm * BM + wm * 64 + mt * 16 + qrow;
        #pragma unroll
        for (int nt = 0; nt < 8; nt++) {
            const int col = bn * BN + wn * 64 + nt * 8 + qcol;
            const float b0 = bias[col], b1 = bias[col + 1];
            float2 v0, v1;
            v0.x = accf[mt][nt][0] * sc + b0;
            v0.y = accf[mt][nt][1] * sc + b1;
            v1.x = accf[mt][nt][2] * sc + b0;
            v1.y = accf[mt][nt][3] * sc + b1;
            *reinterpret_cast<float2*>(out + (size_t)row * NDIM + col) = v0;
            *reinterpret_cast<float2*>(out + (size_t)(row + 8) * NDIM + col) = v1;
        }
    }
}

// ======================= host launch =======================
extern "C" void kernel_launch(void* const* d_in, const int* in_sizes, int n_in,
                              void* d_out, int out_size) {
    const float* x  = (const float*)d_in[0];
    const int*   qw = (const int*)d_in[1];
    const float* sc = (const float*)d_in[2];
    const float* bs = (const float*)d_in[3];
    float* out = (float*)d_out;

    const int M = in_sizes[0] / KDIM;   // 8192

    void *p_xh = nullptr, *p_wh = nullptr;
    cudaGetSymbolAddress(&p_xh, g_xh);
    cudaGetSymbolAddress(&p_wh, g_wh);

    convert_xw_kernel<<<2048, 256>>>(x, qw, (__half*)p_xh, (__half*)p_wh,
                                     (M * KDIM) / 4, (NDIM * KDIM) / 4);

    static bool smem_set = false;
    if (!smem_set) {
        cudaFuncSetAttribute(qlinear_gemm, cudaFuncAttributeMaxDynamicSharedMemorySize, SMEM_TOTAL);
        smem_set = true;
    }
    dim3 grid(NDIM / BN, M / BM);   // (16, 64): bn fastest -> A-row reuse in L2
    qlinear_gemm<<<grid, 256, SMEM_TOTAL>>>(out, sc, bs,
        (const __half*)p_xh, (const __half*)p_wh);
}

// round 14
// speedup vs baseline: 1.3735x; 1.0581x over previous
#include <cuda_runtime.h>
#include <cuda_fp16.h>
#include <cstdint>

// ======================= config =======================
#define BM 128
#define BN 256
#define BK 64                    // fp16 elems per K-chunk: 64*2B = 128B rows
#define STAGES 4

static constexpr int KDIM   = 4096;
static constexpr int NDIM   = 4096;
static constexpr int MMAX   = 8192;
static constexpr int KITERS = KDIM / BK;   // 64

#define A_BYTES     (BM * 128)             // 16384
#define B_BYTES     (BN * 128)             // 32768
#define STAGE_BYTES (A_BYTES + B_BYTES)    // 49152
#define SMEM_TOTAL  (STAGES * STAGE_BYTES) // 196608

// scratch (allocation-free rule: __device__ globals)
__device__ __align__(1024) __half g_xh[(size_t)MMAX * KDIM];  // 64 MiB
__device__ __align__(1024) __half g_wh[(size_t)NDIM * KDIM];  // 32 MiB

// ======================= PTX helpers =======================
__device__ __forceinline__ uint32_t smem_u32(const void* p) {
    uint32_t a;
    asm("{ .reg .u64 t; cvta.to.shared.u64 t, %1; cvt.u32.u64 %0, t; }" : "=r"(a) : "l"(p));
    return a;
}

#define CP_ASYNC16(dst, src) \
    asm volatile("cp.async.cg.shared.global [%0], [%1], 16;" :: "r"(dst), "l"(src) : "memory")
#define CP_COMMIT() asm volatile("cp.async.commit_group;" ::: "memory")
#define CP_WAIT(n)  asm volatile("cp.async.wait_group %0;" :: "n"(n) : "memory")

#define LDSM4(r, addr) \
    asm volatile("ldmatrix.sync.aligned.m8n8.x4.shared.b16 {%0,%1,%2,%3}, [%4];" \
        : "=r"((r)[0]), "=r"((r)[1]), "=r"((r)[2]), "=r"((r)[3]) : "r"(addr))

// f16 x f16 -> f16 accumulate (2x pipe rate vs f32-acc, measured R7)
#define MMA16816_F16(d, a, b0, b1) \
    asm volatile("mma.sync.aligned.m16n8k16.row.col.f16.f16.f16.f16 " \
        "{%0,%1},{%2,%3,%4,%5},{%6,%7},{%0,%1};" \
        : "+r"((d)[0]), "+r"((d)[1]) \
        : "r"((a)[0]), "r"((a)[1]), "r"((a)[2]), "r"((a)[3]), "r"(b0), "r"(b1))

// swizzled smem byte offset: 128B rows, 8x16B chunks, chunk XOR row&7
__device__ __forceinline__ uint32_t swz(int row, int chunk) {
    return (uint32_t)(row * 128 + ((chunk ^ (row & 7)) << 4));
}

// ======================= preprocessing (merged kernel keeps ncu on the GEMM) ===
__global__ void convert_xw_kernel(const float* __restrict__ x,
                                  const int* __restrict__ q,
                                  __half* __restrict__ xh,
                                  __half* __restrict__ wh,
                                  int n4x, int n4w) {
    const int stride = gridDim.x * blockDim.x;
    for (int i = blockIdx.x * blockDim.x + threadIdx.x; i < n4x; i += stride) {
        float4 v = reinterpret_cast<const float4*>(x)[i];
        __half2 h0 = __floats2half2_rn(v.x, v.y);
        __half2 h1 = __floats2half2_rn(v.z, v.w);
        uint2 pk;
        pk.x = *reinterpret_cast<uint32_t*>(&h0);
        pk.y = *reinterpret_cast<uint32_t*>(&h1);
        reinterpret_cast<uint2*>(xh)[i] = pk;
    }
    for (int i = blockIdx.x * blockDim.x + threadIdx.x; i < n4w; i += stride) {
        int4 v = reinterpret_cast<const int4*>(q)[i];
        // q in [0,127): exact in fp16
        __half2 h0 = __floats2half2_rn((float)v.x, (float)v.y);
        __half2 h1 = __floats2half2_rn((float)v.z, (float)v.w);
        uint2 pk;
        pk.x = *reinterpret_cast<uint32_t*>(&h0);
        pk.y = *reinterpret_cast<uint32_t*>(&h1);
        reinterpret_cast<uint2*>(wh)[i] = pk;
    }
}

// ======================= GEMM =======================
__device__ __forceinline__ void load_stage(uint32_t sb, int s, int kn, int tid,
                                           const __half* Ag, const __half* Bg) {
    const uint32_t base = sb + (uint32_t)s * STAGE_BYTES;
    const int row = tid >> 3;          // 0..31
    const int c   = tid & 7;           // 16B chunk
    const int kcol = kn * BK + c * 8;  // fp16 column
    #pragma unroll
    for (int it = 0; it < BM / 32; it++) {          // A: 128 rows
        const int r = row + it * 32;
        CP_ASYNC16(base + swz(r, c), Ag + (size_t)r * KDIM + kcol);
    }
    #pragma unroll
    for (int it = 0; it < BN / 32; it++) {          // B: 256 rows
        const int r = row + it * 32;
        CP_ASYNC16(base + A_BYTES + swz(r, c), Bg + (size_t)r * KDIM + kcol);
    }
    CP_COMMIT();
}

__global__ void __launch_bounds__(256, 1) qlinear_gemm(
    float* __restrict__ out,
    const float* __restrict__ scale,
    const float* __restrict__ bias,
    const __half* __restrict__ Agbase,
    const __half* __restrict__ Bgbase)
{
    extern __shared__ char smem[];
    const uint32_t sb = smem_u32(smem);
    const int tid  = threadIdx.x;
    const int warp = tid >> 5;
    const int lane = tid & 31;
    const int wm   = warp >> 2;        // 0..1  (64-row slab)
    const int wn   = warp & 3;         // 0..3  (64-col slab)
    const int bn   = blockIdx.x;
    const int bm   = blockIdx.y;

    const __half* Ag = Agbase + (size_t)bm * BM * KDIM;
    const __half* Bg = Bgbase + (size_t)bn * BN * KDIM;

    // prologue: fill STAGES-1 stages
    #pragma unroll
    for (int s = 0; s < STAGES - 1; s++) load_stage(sb, s, s, tid, Ag, Bg);

    // f32 master accumulators + per-iter f16 chains
    float accf[4][8][4];
    uint32_t acch[4][8][2];
    #pragma unroll
    for (int mt = 0; mt < 4; mt++)
        #pragma unroll
        for (int nt = 0; nt < 8; nt++) {
            #pragma unroll
            for (int j = 0; j < 4; j++) accf[mt][nt][j] = 0.f;
            acch[mt][nt][0] = 0u;
            acch[mt][nt][1] = 0u;
        }

    const int arow0 = wm * 64 + (lane & 15);
    const int brow0 = wn * 64 + (lane & 15);
    const int chi   = lane >> 4;       // 0/1: k8-chunk within k16

    // single-buffered fragments, live across the barrier (pipelined ks0)
    uint32_t a[4][4], b[4][4];

    // prologue sync: stages 0 AND 1 visible (wait(1): done >= 2 groups)
    CP_WAIT(1);
    __syncthreads();

    // prefetch ks0 fragments of stage 0
    #pragma unroll
    for (int mt = 0; mt < 4; mt++)
        LDSM4(a[mt], sb + swz(arow0 + mt * 16, chi));
    #pragma unroll
    for (int bi = 0; bi < 4; bi++)
        LDSM4(b[bi], sb + A_BYTES + swz(brow0 + bi * 16, chi));

    for (int kn = 0; kn < KITERS; kn++) {
        const uint32_t abase = sb + (uint32_t)(kn & 3) * STAGE_BYTES;
        const uint32_t bbase = abase + A_BYTES;

        // ---- ks0: fragments already prefetched last iteration ----
        #pragma unroll
        for (int mt = 0; mt < 4; mt++)
            #pragma unroll
            for (int nt = 0; nt < 8; nt++) {
                const int bi = nt >> 1, sel = nt & 1;
                MMA16816_F16(acch[mt][nt], a[mt], b[bi][sel], b[bi][sel + 2]);
            }

        // ---- ks = 1..3 ----
        #pragma unroll
        for (int ks = 1; ks < 4; ks++) {
            const int kc = ks * 2 + chi;
            #pragma unroll
            for (int mt = 0; mt < 4; mt++)
                LDSM4(a[mt], abase + swz(arow0 + mt * 16, kc));
            #pragma unroll
            for (int bi = 0; bi < 4; bi++)
                LDSM4(b[bi], bbase + swz(brow0 + bi * 16, kc));
            #pragma unroll
            for (int mt = 0; mt < 4; mt++)
                #pragma unroll
                for (int nt = 0; nt < 8; nt++) {
                    const int bi = nt >> 1, sel = nt & 1;
                    MMA16816_F16(acch[mt][nt], a[mt], b[bi][sel], b[bi][sel + 2]);
                }
        }

        // issue next-stage copy into slot (kn+3)&3 = (kn-1)&3
        // (safe: all reads of stage kn-1 confirmed by previous barrier)
        if (kn + STAGES - 1 < KITERS)
            load_stage(sb, (kn + STAGES - 1) & 3, kn + STAGES - 1, tid, Ag, Bg);
        else
            CP_COMMIT();   // keep group count consistent

        // ---- prefetch ks0 of stage kn+1 (visibility established at the
        //      previous barrier: wait(1) guarantees stages <= kn+1 done).
        //      On the last iter this reads stale slot 0 -- harmless, unused. ----
        {
            const uint32_t nabase = sb + (uint32_t)((kn + 1) & 3) * STAGE_BYTES;
            const uint32_t nbbase = nabase + A_BYTES;
            #pragma unroll
            for (int mt = 0; mt < 4; mt++)
                LDSM4(a[mt], nabase + swz(arow0 + mt * 16, chi));
            #pragma unroll
            for (int bi = 0; bi < 4; bi++)
                LDSM4(b[bi], nbbase + swz(brow0 + bi * 16, chi));
        }

        // ---- drain f16 chain -> f32 masters (in the prefetch-LDSM shadow) ----
        #pragma unroll
        for (int mt = 0; mt < 4; mt++)
            #pragma unroll
            for (int nt = 0; nt < 8; nt++) {
                const float2 f0 = __half22float2(*reinterpret_cast<__half2*>(&acch[mt][nt][0]));
                const float2 f1 = __half22float2(*reinterpret_cast<__half2*>(&acch[mt][nt][1]));
                accf[mt][nt][0] += f0.x;
                accf[mt][nt][1] += f0.y;
                accf[mt][nt][2] += f1.x;
                accf[mt][nt][3] += f1.y;
                acch[mt][nt][0] = 0u;
                acch[mt][nt][1] = 0u;
            }

        // end-of-iter barrier: publishes stage kn+2 (wait(1): done >= kn+3 groups)
        CP_WAIT(1);
        __syncthreads();
    }

    // ---------- epilogue: y = accf*scale + bias ----------
    const float sc = scale[0];
    const int qrow = lane >> 2;          // 0..7
    const int qcol = (lane & 3) * 2;     // 0,2,4,6

    #pragma unroll
    for (int mt = 0; mt < 4; mt++) {
        const int row = bm * BM + wm * 64 + mt * 16 + qrow;
        #pragma unroll
        for (int nt = 0; nt < 8; nt++) {
            const int col = bn * BN + wn * 64 + nt * 8 + qcol;
            const float b0 = bias[col], b1 = bias[col + 1];
            float2 v0, v1;
            v0.x = accf[mt][nt][0] * sc + b0;
            v0.y = accf[mt][nt][1] * sc + b1;
            v1.x = accf[mt][nt][2] * sc + b0;
            v1.y = accf[mt][nt][3] * sc + b1;
            *reinterpret_cast<float2*>(out + (size_t)row * NDIM + col) = v0;
            *reinterpret_cast<float2*>(out + (size_t)(row + 8) * NDIM + col) = v1;
        }
    }
}

// ======================= host launch =======================
extern "C" void kernel_launch(void* const* d_in, const int* in_sizes, int n_in,
                              void* d_out, int out_size) {
    const float* x  = (const float*)d_in[0];
    const int*   qw = (const int*)d_in[1];
    const float* sc = (const float*)d_in[2];
    const float* bs = (const float*)d_in[3];
    float* out = (float*)d_out;

    const int M = in_sizes[0] / KDIM;   // 8192

    void *p_xh = nullptr, *p_wh = nullptr;
    cudaGetSymbolAddress(&p_xh, g_xh);
    cudaGetSymbolAddress(&p_wh, g_wh);

    convert_xw_kernel<<<2048, 256>>>(x, qw, (__half*)p_xh, (__half*)p_wh,
                                     (M * KDIM) / 4, (NDIM * KDIM) / 4);

    static bool smem_set = false;
    if (!smem_set) {
        cudaFuncSetAttribute(qlinear_gemm, cudaFuncAttributeMaxDynamicSharedMemorySize, SMEM_TOTAL);
        smem_set = true;
    }
    dim3 grid(NDIM / BN, M / BM);   // (16, 64): bn fastest -> A-row reuse in L2
    qlinear_gemm<<<grid, 256, SMEM_TOTAL>>>(out, sc, bs,
        (const __half*)p_xh, (const __half*)p_wh);
}

// round 15
// speedup vs baseline: 1.5105x; 1.0998x over previous
#include <cuda_runtime.h>
#include <cuda_fp16.h>
#include <cstdint>

// ======================= config =======================
#define BM 128
#define BN 256
#define BK 64                    // fp16 elems per K-chunk: 64*2B = 128B rows
#define STAGES 4

static constexpr int KDIM   = 4096;
static constexpr int NDIM   = 4096;
static constexpr int MMAX   = 8192;
static constexpr int KITERS = KDIM / BK;   // 64

#define A_BYTES     (BM * 128)             // 16384
#define B_BYTES     (BN * 128)             // 32768
#define STAGE_BYTES (A_BYTES + B_BYTES)    // 49152
#define SMEM_TOTAL  (STAGES * STAGE_BYTES) // 196608

// scratch (allocation-free rule: __device__ globals)
__device__ __align__(1024) __half g_xh[(size_t)MMAX * KDIM];  // 64 MiB
__device__ __align__(1024) __half g_wh[(size_t)NDIM * KDIM];  // 32 MiB

// ======================= PTX helpers =======================
__device__ __forceinline__ uint32_t smem_u32(const void* p) {
    uint32_t a;
    asm("{ .reg .u64 t; cvta.to.shared.u64 t, %1; cvt.u32.u64 %0, t; }" : "=r"(a) : "l"(p));
    return a;
}

#define CP_ASYNC16(dst, src) \
    asm volatile("cp.async.cg.shared.global [%0], [%1], 16;" :: "r"(dst), "l"(src) : "memory")
#define CP_COMMIT() asm volatile("cp.async.commit_group;" ::: "memory")
#define CP_WAIT(n)  asm volatile("cp.async.wait_group %0;" :: "n"(n) : "memory")

#define LDSM4(r, addr) \
    asm volatile("ldmatrix.sync.aligned.m8n8.x4.shared.b16 {%0,%1,%2,%3}, [%4];" \
        : "=r"((r)[0]), "=r"((r)[1]), "=r"((r)[2]), "=r"((r)[3]) : "r"(addr))

// f16 x f16 -> f16 accumulate (2x pipe rate vs f32-acc, measured R7)
#define MMA16816_F16(d, a, b0, b1) \
    asm volatile("mma.sync.aligned.m16n8k16.row.col.f16.f16.f16.f16 " \
        "{%0,%1},{%2,%3,%4,%5},{%6,%7},{%0,%1};" \
        : "+r"((d)[0]), "+r"((d)[1]) \
        : "r"((a)[0]), "r"((a)[1]), "r"((a)[2]), "r"((a)[3]), "r"(b0), "r"(b1))

// swizzled smem byte offset: 128B rows, 8x16B chunks, chunk XOR row&7
__device__ __forceinline__ uint32_t swz(int row, int chunk) {
    return (uint32_t)(row * 128 + ((chunk ^ (row & 7)) << 4));
}

// ======================= preprocessing (merged kernel keeps ncu on the GEMM) ===
__global__ void convert_xw_kernel(const float* __restrict__ x,
                                  const int* __restrict__ q,
                                  __half* __restrict__ xh,
                                  __half* __restrict__ wh,
                                  int n4x, int n4w) {
    const int stride = gridDim.x * blockDim.x;
    for (int i = blockIdx.x * blockDim.x + threadIdx.x; i < n4x; i += stride) {
        float4 v = reinterpret_cast<const float4*>(x)[i];
        __half2 h0 = __floats2half2_rn(v.x, v.y);
        __half2 h1 = __floats2half2_rn(v.z, v.w);
        uint2 pk;
        pk.x = *reinterpret_cast<uint32_t*>(&h0);
        pk.y = *reinterpret_cast<uint32_t*>(&h1);
        reinterpret_cast<uint2*>(xh)[i] = pk;
    }
    for (int i = blockIdx.x * blockDim.x + threadIdx.x; i < n4w; i += stride) {
        int4 v = reinterpret_cast<const int4*>(q)[i];
        // q in [0,127): exact in fp16
        __half2 h0 = __floats2half2_rn((float)v.x, (float)v.y);
        __half2 h1 = __floats2half2_rn((float)v.z, (float)v.w);
        uint2 pk;
        pk.x = *reinterpret_cast<uint32_t*>(&h0);
        pk.y = *reinterpret_cast<uint32_t*>(&h1);
        reinterpret_cast<uint2*>(wh)[i] = pk;
    }
}

// ======================= GEMM =======================
__device__ __forceinline__ void load_stage(uint32_t sb, int s, int kn, int tid,
                                           const __half* Ag, const __half* Bg) {
    const uint32_t base = sb + (uint32_t)s * STAGE_BYTES;
    const int row = tid >> 3;          // 0..31
    const int c   = tid & 7;           // 16B chunk
    const int kcol = kn * BK + c * 8;  // fp16 column
    #pragma unroll
    for (int it = 0; it < BM / 32; it++) {          // A: 128 rows
        const int r = row + it * 32;
        CP_ASYNC16(base + swz(r, c), Ag + (size_t)r * KDIM + kcol);
    }
    #pragma unroll
    for (int it = 0; it < BN / 32; it++) {          // B: 256 rows
        const int r = row + it * 32;
        CP_ASYNC16(base + A_BYTES + swz(r, c), Bg + (size_t)r * KDIM + kcol);
    }
    CP_COMMIT();
}

// one k-iteration; GRP selects which half of the tiles drains (staggered
// 2-iter f16 chains: nt[0,4) on even kn, nt[4,8) on odd kn -> K=128 chains)
#define ITER_BODY(KN, GRP) do {                                                      \
    const uint32_t abase = sb + (uint32_t)((KN) & 3) * STAGE_BYTES;                  \
    const uint32_t bbase = abase + A_BYTES;                                          \
    /* ks0: fragments already prefetched last iteration */                           \
    _Pragma("unroll")                                                                \
    for (int mt = 0; mt < 4; mt++)                                                   \
        _Pragma("unroll")                                                            \
        for (int nt = 0; nt < 8; nt++) {                                             \
            const int bi = nt >> 1, sel = nt & 1;                                    \
            MMA16816_F16(acch[mt][nt], a[mt], b[bi][sel], b[bi][sel + 2]);           \
        }                                                                            \
    /* ks = 1..3 */                                                                  \
    _Pragma("unroll")                                                                \
    for (int ks = 1; ks < 4; ks++) {                                                 \
        const int kc = ks * 2 + chi;                                                 \
        _Pragma("unroll")                                                            \
        for (int mt = 0; mt < 4; mt++)                                               \
            LDSM4(a[mt], abase + swz(arow0 + mt * 16, kc));                          \
        _Pragma("unroll")                                                            \
        for (int bi = 0; bi < 4; bi++)                                               \
            LDSM4(b[bi], bbase + swz(brow0 + bi * 16, kc));                          \
        _Pragma("unroll")                                                            \
        for (int mt = 0; mt < 4; mt++)                                               \
            _Pragma("unroll")                                                        \
            for (int nt = 0; nt < 8; nt++) {                                         \
                const int bi = nt >> 1, sel = nt & 1;                                \
                MMA16816_F16(acch[mt][nt], a[mt], b[bi][sel], b[bi][sel + 2]);       \
            }                                                                        \
    }                                                                                \
    /* next-stage copy into slot (KN+3)&3 (reads confirmed by prev barrier) */      \
    if ((KN) + STAGES - 1 < KITERS)                                                  \
        load_stage(sb, ((KN) + STAGES - 1) & 3, (KN) + STAGES - 1, tid, Ag, Bg);     \
    else                                                                             \
        CP_COMMIT();                                                                 \
    /* prefetch ks0 of stage KN+1 (visible since prev barrier) */                    \
    {                                                                                \
        const uint32_t nabase = sb + (uint32_t)(((KN) + 1) & 3) * STAGE_BYTES;       \
        const uint32_t nbbase = nabase + A_BYTES;                                    \
        _Pragma("unroll")                                                            \
        for (int mt = 0; mt < 4; mt++)                                               \
            LDSM4(a[mt], nabase + swz(arow0 + mt * 16, chi));                        \
        _Pragma("unroll")                                                            \
        for (int bi = 0; bi < 4; bi++)                                               \
            LDSM4(b[bi], nbbase + swz(brow0 + bi * 16, chi));                        \
    }                                                                                \
    /* drain HALF the tiles (this group's chains span 2 k-iters = K=128) */         \
    _Pragma("unroll")                                                                \
    for (int mt = 0; mt < 4; mt++)                                                   \
        _Pragma("unroll")                                                            \
        for (int nt = (GRP) * 4; nt < (GRP) * 4 + 4; nt++) {                         \
            const float2 f0 = __half22float2(*reinterpret_cast<__half2*>(&acch[mt][nt][0])); \
            const float2 f1 = __half22float2(*reinterpret_cast<__half2*>(&acch[mt][nt][1])); \
            accf[mt][nt][0] += f0.x;                                                 \
            accf[mt][nt][1] += f0.y;                                                 \
            accf[mt][nt][2] += f1.x;                                                 \
            accf[mt][nt][3] += f1.y;                                                 \
            acch[mt][nt][0] = 0u;                                                    \
            acch[mt][nt][1] = 0u;                                                    \
        }                                                                            \
    CP_WAIT(1);                                                                      \
    __syncthreads();                                                                 \
} while (0)

__global__ void __launch_bounds__(256, 1) qlinear_gemm(
    float* __restrict__ out,
    const float* __restrict__ scale,
    const float* __restrict__ bias,
    const __half* __restrict__ Agbase,
    const __half* __restrict__ Bgbase)
{
    extern __shared__ char smem[];
    const uint32_t sb = smem_u32(smem);
    const int tid  = threadIdx.x;
    const int warp = tid >> 5;
    const int lane = tid & 31;
    const int wm   = warp >> 2;        // 0..1  (64-row slab)
    const int wn   = warp & 3;         // 0..3  (64-col slab)
    const int bn   = blockIdx.x;
    const int bm   = blockIdx.y;

    const __half* Ag = Agbase + (size_t)bm * BM * KDIM;
    const __half* Bg = Bgbase + (size_t)bn * BN * KDIM;

    // prologue: fill STAGES-1 stages
    #pragma unroll
    for (int s = 0; s < STAGES - 1; s++) load_stage(sb, s, s, tid, Ag, Bg);

    // f32 masters + f16 chain accumulators
    float accf[4][8][4];
    uint32_t acch[4][8][2];
    #pragma unroll
    for (int mt = 0; mt < 4; mt++)
        #pragma unroll
        for (int nt = 0; nt < 8; nt++) {
            #pragma unroll
            for (int j = 0; j < 4; j++) accf[mt][nt][j] = 0.f;
            acch[mt][nt][0] = 0u;
            acch[mt][nt][1] = 0u;
        }

    const int arow0 = wm * 64 + (lane & 15);
    const int brow0 = wn * 64 + (lane & 15);
    const int chi   = lane >> 4;       // 0/1: k8-chunk within k16

    // single-buffered fragments, live across the barrier (pipelined ks0)
    uint32_t a[4][4], b[4][4];

    // prologue sync: stages 0 AND 1 visible (wait(1): done >= 2 groups)
    CP_WAIT(1);
    __syncthreads();

    // prefetch ks0 fragments of stage 0
    #pragma unroll
    for (int mt = 0; mt < 4; mt++)
        LDSM4(a[mt], sb + swz(arow0 + mt * 16, chi));
    #pragma unroll
    for (int bi = 0; bi < 4; bi++)
        LDSM4(b[bi], sb + A_BYTES + swz(brow0 + bi * 16, chi));

    for (int kn2 = 0; kn2 < KITERS; kn2 += 2) {
        ITER_BODY(kn2,     0);   // even iter: drain nt 0..3
        ITER_BODY(kn2 + 1, 1);   // odd  iter: drain nt 4..7
    }

    // final drain: group0 chains still hold iters 62,63
    #pragma unroll
    for (int mt = 0; mt < 4; mt++)
        #pragma unroll
        for (int nt = 0; nt < 4; nt++) {
            const float2 f0 = __half22float2(*reinterpret_cast<__half2*>(&acch[mt][nt][0]));
            const float2 f1 = __half22float2(*reinterpret_cast<__half2*>(&acch[mt][nt][1]));
            accf[mt][nt][0] += f0.x;
            accf[mt][nt][1] += f0.y;
            accf[mt][nt][2] += f1.x;
            accf[mt][nt][3] += f1.y;
        }

    // ---------- epilogue: y = accf*scale + bias ----------
    const float sc = scale[0];
    const int qrow = lane >> 2;          // 0..7
    const int qcol = (lane & 3) * 2;     // 0,2,4,6

    #pragma unroll
    for (int mt = 0; mt < 4; mt++) {
        const int row = bm * BM + wm * 64 + mt * 16 + qrow;
        #pragma unroll
        for (int nt = 0; nt < 8; nt++) {
            const int col = bn * BN + wn * 64 + nt * 8 + qcol;
            const float b0 = bias[col], b1 = bias[col + 1];
            float2 v0, v1;
            v0.x = accf[mt][nt][0] * sc + b0;
            v0.y = accf[mt][nt][1] * sc + b1;
            v1.x = accf[mt][nt][2] * sc + b0;
            v1.y = accf[mt][nt][3] * sc + b1;
            *reinterpret_cast<float2*>(out + (size_t)row * NDIM + col) = v0;
            *reinterpret_cast<float2*>(out + (size_t)(row + 8) * NDIM + col) = v1;
        }
    }
}

// ======================= host launch =======================
extern "C" void kernel_launch(void* const* d_in, const int* in_sizes, int n_in,
                              void* d_out, int out_size) {
    const float* x  = (const float*)d_in[0];
    const int*   qw = (const int*)d_in[1];
    const float* sc = (const float*)d_in[2];
    const float* bs = (const float*)d_in[3];
    float* out = (float*)d_out;

    const int M = in_sizes[0] / KDIM;   // 8192

    void *p_xh = nullptr, *p_wh = nullptr;
    cudaGetSymbolAddress(&p_xh, g_xh);
    cudaGetSymbolAddress(&p_wh, g_wh);

    convert_xw_kernel<<<2048, 256>>>(x, qw, (__half*)p_xh, (__half*)p_wh,
                                     (M * KDIM) / 4, (NDIM * KDIM) / 4);

    static bool smem_set = false;
    if (!smem_set) {
        cudaFuncSetAttribute(qlinear_gemm, cudaFuncAttributeMaxDynamicSharedMemorySize, SMEM_TOTAL);
        smem_set = true;
    }
    dim3 grid(NDIM / BN, M / BM);   // (16, 64): bn fastest -> A-row reuse in L2
    qlinear_gemm<<<grid, 256, SMEM_TOTAL>>>(out, sc, bs,
        (const __half*)p_xh, (const __half*)p_wh);
}